// round 1
// baseline (speedup 1.0000x reference)
#include <cuda_runtime.h>
#include <cuda_bf16.h>
#include <cstdint>

// Problem constants (fixed shapes from reference)
#define Bn 4
#define Cn 32
#define Hn 544
#define Wn 960
#define HWn (Hn * Wn)          // 522240
#define NPIX (Bn * HWn)        // 2088960
#define NOUT (Bn * Cn * HWn)   // 66846720

// Norm-channel scratch (accumulates splatted exp(metric)); zeroed each launch.
__device__ float g_norm[NPIX];

// ---------------------------------------------------------------------------
// Scatter: one thread per source pixel. Computes bilinear splat weights,
// scales by m = exp(metric), and atomically accumulates 32 channels + norm.
// ---------------------------------------------------------------------------
__global__ __launch_bounds__(256) void softsplat_scatter(
    const float* __restrict__ in,     // [B,32,H,W]
    const float* __restrict__ flow,   // [B,2,H,W]
    const float* __restrict__ metric, // [B,1,H,W]
    float* __restrict__ out,          // [B,32,H,W] (pre-zeroed)
    float* __restrict__ norm)         // [B,H,W]    (pre-zeroed)
{
    int idx = blockIdx.x * blockDim.x + threadIdx.x;
    if (idx >= NPIX) return;

    int b = idx / HWn;
    int p = idx - b * HWn;
    int y = p / Wn;
    int x = p - y * Wn;

    float fx = flow[(size_t)(b * 2 + 0) * HWn + p];
    float fy = flow[(size_t)(b * 2 + 1) * HWn + p];

    float ox = (float)x + fx;
    float oy = (float)y + fy;

    float x0f = floorf(ox);
    float y0f = floorf(oy);
    int x0 = (int)x0f;
    int y0 = (int)y0f;
    int x1 = x0 + 1;
    int y1 = y0 + 1;

    float ax = ox - x0f;          // in [0,1)
    float ay = oy - y0f;
    float bx = 1.0f - ax;
    float by = 1.0f - ay;

    float m = __expf(metric[(size_t)b * HWn + p]);

    // corner scale factors (include m)
    float s00 = m * (bx * by);    // (x0, y0)
    float s01 = m * (ax * by);    // (x1, y0)
    float s10 = m * (bx * ay);    // (x0, y1)
    float s11 = m * (ax * ay);    // (x1, y1)

    bool vx0 = ((unsigned)x0 < (unsigned)Wn);
    bool vx1 = ((unsigned)x1 < (unsigned)Wn);
    bool vy0 = ((unsigned)y0 < (unsigned)Hn);
    bool vy1 = ((unsigned)y1 < (unsigned)Hn);

    bool v00 = vx0 && vy0;
    bool v01 = vx1 && vy0;
    bool v10 = vx0 && vy1;
    bool v11 = vx1 && vy1;

    if (!(v00 | v01 | v10 | v11)) return;

    int o00 = y0 * Wn + x0;
    int o01 = y0 * Wn + x1;
    int o10 = y1 * Wn + x0;
    int o11 = y1 * Wn + x1;

    float* nb = norm + (size_t)b * HWn;
    if (v00) atomicAdd(nb + o00, s00);
    if (v01) atomicAdd(nb + o01, s01);
    if (v10) atomicAdd(nb + o10, s10);
    if (v11) atomicAdd(nb + o11, s11);

    const float* ip = in + (size_t)b * Cn * HWn + p;
    float* op = out + (size_t)b * Cn * HWn;

#pragma unroll 8
    for (int c = 0; c < Cn; ++c) {
        float v = __ldg(ip + (size_t)c * HWn);
        size_t cb = (size_t)c * HWn;
        if (v00) atomicAdd(op + cb + o00, v * s00);
        if (v01) atomicAdd(op + cb + o01, v * s01);
        if (v10) atomicAdd(op + cb + o10, v * s10);
        if (v11) atomicAdd(op + cb + o11, v * s11);
    }
}

// ---------------------------------------------------------------------------
// Normalize: out /= (norm == 0 ? 1 : norm), float4 vectorized.
// NOUT % 4 == 0, HWn % 4 == 0, so channel/pixel alignment holds per vec4.
// ---------------------------------------------------------------------------
__global__ __launch_bounds__(256) void softsplat_normalize(
    float* __restrict__ out,
    const float* __restrict__ norm)
{
    int idx = blockIdx.x * blockDim.x + threadIdx.x; // vec4 index
    const int nvec = NOUT / 4;
    if (idx >= nvec) return;

    int e0 = idx * 4;
    int b = e0 / (Cn * HWn);
    int p = e0 % HWn;  // pixel offset of first element; 4 consecutive pixels

    const float4 nv = *reinterpret_cast<const float4*>(norm + (size_t)b * HWn + p);
    float4 ov = *reinterpret_cast<float4*>(out + e0);

    ov.x = ov.x / (nv.x == 0.0f ? 1.0f : nv.x);
    ov.y = ov.y / (nv.y == 0.0f ? 1.0f : nv.y);
    ov.z = ov.z / (nv.z == 0.0f ? 1.0f : nv.z);
    ov.w = ov.w / (nv.w == 0.0f ? 1.0f : nv.w);

    *reinterpret_cast<float4*>(out + e0) = ov;
}

extern "C" void kernel_launch(void* const* d_in, const int* in_sizes, int n_in,
                              void* d_out, int out_size) {
    const float* in     = (const float*)d_in[0];
    const float* flow   = (const float*)d_in[1];
    const float* metric = (const float*)d_in[2];
    float* out = (float*)d_out;

    float* normPtr = nullptr;
    cudaGetSymbolAddress((void**)&normPtr, g_norm);

    cudaMemsetAsync(out, 0, (size_t)out_size * sizeof(float), 0);
    cudaMemsetAsync(normPtr, 0, (size_t)NPIX * sizeof(float), 0);

    {
        int threads = 256;
        int blocks = (NPIX + threads - 1) / threads;
        softsplat_scatter<<<blocks, threads>>>(in, flow, metric, out, normPtr);
    }
    {
        int threads = 256;
        int nvec = NOUT / 4;
        int blocks = (nvec + threads - 1) / threads;
        softsplat_normalize<<<blocks, threads>>>(out, normPtr);
    }
}

// round 2
// speedup vs baseline: 2.1209x; 2.1209x over previous
#include <cuda_runtime.h>
#include <cuda_bf16.h>
#include <cstdint>

// Problem constants (fixed shapes from reference)
#define Bn 4
#define Cn 32
#define Hn 544
#define Wn 960
#define HWn (Hn * Wn)          // 522240
#define NPIX (Bn * HWn)        // 2088960
#define NOUT (Bn * Cn * HWn)   // 66846720

// NHWC accumulation scratch: [B, HW, 32] floats (zeroed each launch).
// Declared as float4 to guarantee 16B alignment for vector atomics.
__device__ float4 g_scratch[NOUT / 4];
// Norm-channel scratch (splatted exp(metric)), [B, HW].
__device__ float g_norm[NPIX];

// Vector reduction: 4-wide fp32 add to global memory (sm_90+).
__device__ __forceinline__ void red_add_v4(float* p, float a, float b, float c, float d) {
    asm volatile("red.global.add.v4.f32 [%0], {%1, %2, %3, %4};"
                 :: "l"(p), "f"(a), "f"(b), "f"(c), "f"(d) : "memory");
}
__device__ __forceinline__ void red_add_f32(float* p, float a) {
    asm volatile("red.global.add.f32 [%0], %1;" :: "l"(p), "f"(a) : "memory");
}

// ---------------------------------------------------------------------------
// Scatter: one thread per source pixel. NHWC destination -> each corner is
// 8 vec4 atomics over 128 contiguous bytes (one L2 line).
// ---------------------------------------------------------------------------
__global__ __launch_bounds__(256) void softsplat_scatter(
    const float* __restrict__ in,     // [B,32,H,W]
    const float* __restrict__ flow,   // [B,2,H,W]
    const float* __restrict__ metric, // [B,1,H,W]
    float* __restrict__ scratch,      // [B,HW,32] (pre-zeroed)
    float* __restrict__ norm)         // [B,HW]    (pre-zeroed)
{
    int idx = blockIdx.x * blockDim.x + threadIdx.x;
    if (idx >= NPIX) return;

    int b = idx / HWn;
    int p = idx - b * HWn;
    int y = p / Wn;
    int x = p - y * Wn;

    float fx = flow[(size_t)(b * 2 + 0) * HWn + p];
    float fy = flow[(size_t)(b * 2 + 1) * HWn + p];

    float ox = (float)x + fx;
    float oy = (float)y + fy;

    float x0f = floorf(ox);
    float y0f = floorf(oy);
    int x0 = (int)x0f;
    int y0 = (int)y0f;
    int x1 = x0 + 1;
    int y1 = y0 + 1;

    float ax = ox - x0f;
    float ay = oy - y0f;
    float bx = 1.0f - ax;
    float by = 1.0f - ay;

    float m = __expf(metric[(size_t)b * HWn + p]);

    float s00 = m * (bx * by);    // (x0, y0)
    float s01 = m * (ax * by);    // (x1, y0)
    float s10 = m * (bx * ay);    // (x0, y1)
    float s11 = m * (ax * ay);    // (x1, y1)

    bool v00 = ((unsigned)x0 < (unsigned)Wn) && ((unsigned)y0 < (unsigned)Hn);
    bool v01 = ((unsigned)x1 < (unsigned)Wn) && ((unsigned)y0 < (unsigned)Hn);
    bool v10 = ((unsigned)x0 < (unsigned)Wn) && ((unsigned)y1 < (unsigned)Hn);
    bool v11 = ((unsigned)x1 < (unsigned)Wn) && ((unsigned)y1 < (unsigned)Hn);

    if (!(v00 | v01 | v10 | v11)) return;

    size_t bb = (size_t)b * HWn;
    float* d00 = scratch + (bb + (size_t)(y0 * Wn + x0)) * Cn;
    float* d01 = scratch + (bb + (size_t)(y0 * Wn + x1)) * Cn;
    float* d10 = scratch + (bb + (size_t)(y1 * Wn + x0)) * Cn;
    float* d11 = scratch + (bb + (size_t)(y1 * Wn + x1)) * Cn;

    float* nb = norm + bb;
    if (v00) red_add_f32(nb + (y0 * Wn + x0), s00);
    if (v01) red_add_f32(nb + (y0 * Wn + x1), s01);
    if (v10) red_add_f32(nb + (y1 * Wn + x0), s10);
    if (v11) red_add_f32(nb + (y1 * Wn + x1), s11);

    const float* ip = in + (size_t)b * Cn * HWn + p;

#pragma unroll
    for (int c0 = 0; c0 < Cn; c0 += 4) {
        float a0 = __ldg(ip + (size_t)(c0 + 0) * HWn);
        float a1 = __ldg(ip + (size_t)(c0 + 1) * HWn);
        float a2 = __ldg(ip + (size_t)(c0 + 2) * HWn);
        float a3 = __ldg(ip + (size_t)(c0 + 3) * HWn);
        if (v00) red_add_v4(d00 + c0, a0 * s00, a1 * s00, a2 * s00, a3 * s00);
        if (v01) red_add_v4(d01 + c0, a0 * s01, a1 * s01, a2 * s01, a3 * s01);
        if (v10) red_add_v4(d10 + c0, a0 * s10, a1 * s10, a2 * s10, a3 * s10);
        if (v11) red_add_v4(d11 + c0, a0 * s11, a1 * s11, a2 * s11, a3 * s11);
    }
}

// ---------------------------------------------------------------------------
// Normalize + transpose NHWC -> NCHW.
// Block = 256 threads, processes 128 pixels x 32 channels (16K floats).
// Load: fully coalesced float4 reads of NHWC scratch into padded smem tile.
// Store: fully coalesced float4 writes per channel row, scaled by 1/norm.
// ---------------------------------------------------------------------------
#define TPAD 133   // 133 % 32 = 5 -> conflict-free column writes

__global__ __launch_bounds__(256) void softsplat_normalize_t(
    const float* __restrict__ scratch, // [B,HW,32]
    const float* __restrict__ norm,    // [B,HW]
    float* __restrict__ out)           // [B,32,H,W]
{
    __shared__ float tile[Cn][TPAD];   // [c][pix] but pix dim=128 (TPAD>=128)
    __shared__ float rn[128];

    const int t = threadIdx.x;
    const int blocksPerImage = HWn / 128;           // 4080
    const int b = blockIdx.x / blocksPerImage;
    const int p0 = (blockIdx.x % blocksPerImage) * 128;

    // Load 128 pixels x 32 channels = 1024 float4s; 4 per thread.
    const float4* src = reinterpret_cast<const float4*>(
        scratch + ((size_t)b * HWn + p0) * Cn);
#pragma unroll
    for (int k = 0; k < 4; ++k) {
        int f4 = t + k * 256;              // float4 index within block chunk
        float4 v = src[f4];
        int e = f4 * 4;                    // element index
        int pix = e >> 5;                  // e / 32
        int c = e & 31;                    // consecutive c for the 4 lanes
        tile[c + 0][pix] = v.x;
        tile[c + 1][pix] = v.y;
        tile[c + 2][pix] = v.z;
        tile[c + 3][pix] = v.w;
    }

    // Reciprocal norm per pixel.
    if (t < 128) {
        float nv = norm[(size_t)b * HWn + p0 + t];
        rn[t] = (nv == 0.0f) ? 1.0f : (1.0f / nv);
    }
    __syncthreads();

    // Write NCHW: flat f = c*32 + q ; q indexes float4 within the 128-pixel row.
    float* ob = out + (size_t)b * Cn * HWn + p0;
#pragma unroll
    for (int k = 0; k < 4; ++k) {
        int f = t + k * 256;
        int c = f >> 5;
        int q = f & 31;
        int px = q * 4;
        float4 o;
        o.x = tile[c][px + 0] * rn[px + 0];
        o.y = tile[c][px + 1] * rn[px + 1];
        o.z = tile[c][px + 2] * rn[px + 2];
        o.w = tile[c][px + 3] * rn[px + 3];
        *reinterpret_cast<float4*>(ob + (size_t)c * HWn + px) = o;
    }
}

extern "C" void kernel_launch(void* const* d_in, const int* in_sizes, int n_in,
                              void* d_out, int out_size) {
    const float* in     = (const float*)d_in[0];
    const float* flow   = (const float*)d_in[1];
    const float* metric = (const float*)d_in[2];
    float* out = (float*)d_out;

    float* scratchPtr = nullptr;
    float* normPtr = nullptr;
    cudaGetSymbolAddress((void**)&scratchPtr, g_scratch);
    cudaGetSymbolAddress((void**)&normPtr, g_norm);

    cudaMemsetAsync(scratchPtr, 0, (size_t)NOUT * sizeof(float), 0);
    cudaMemsetAsync(normPtr, 0, (size_t)NPIX * sizeof(float), 0);

    {
        int threads = 256;
        int blocks = (NPIX + threads - 1) / threads;
        softsplat_scatter<<<blocks, threads>>>(in, flow, metric, scratchPtr, normPtr);
    }
    {
        int threads = 256;
        int blocks = (Bn * HWn) / 128;   // 16320
        softsplat_normalize_t<<<blocks, threads>>>(scratchPtr, normPtr, out);
    }
}